// round 6
// baseline (speedup 1.0000x reference)
#include <cuda_runtime.h>

// CutStripes: out[b, :, t, :] = x[perm[b], :, t, :] if t falls inside any of 4
// stripes [bgn[b,s], bgn[b,s]+distance[b,s]), else x[b, :, t, :].
// Shapes: B=128, C=1, T=2048, F=128, STRIPES=4.
//
// R5: persistent grid-stride launch. Grid sized to residency (148 SMs x 8
// blocks of 256 thr, regs~40 -> all resident in one wave). Each warp loops
// over 8-row groups with stride = total warps. This removes the 4.6
// occupancy-wave transitions of the one-shot 4096-block launch and lets ptxas
// pipeline the next iteration's 8 LDG.128s above the current iteration's
// stores, keeping loads continuously in flight across group boundaries.

#define T_DIM         2048
#define F4            32        // 128 floats / 4
#define STRIPES       4
#define ROWS_PER_WARP 8
#define WARPS_PER_BLK 8
#define NUM_BLOCKS    1184      // 148 SMs * 8 resident blocks
#define TOTAL_WARPS   (NUM_BLOCKS * WARPS_PER_BLK)   // 9472
#define NUM_GROUPS    (128 * T_DIM / ROWS_PER_WARP)  // 32768

__global__ __launch_bounds__(256) void cutstripes_kernel(
    const float4* __restrict__ x,
    const int*    __restrict__ perm,
    const int*    __restrict__ bgn,
    const int*    __restrict__ dist,
    float4*       __restrict__ out)
{
    const int warp0 = (blockIdx.x * blockDim.x + threadIdx.x) >> 5;
    const int lane  = threadIdx.x & 31;
    const int k = lane >> 2;       // row within group this lane checks
    const int s = lane & 3;        // stripe this lane checks

    for (int g = warp0; g < NUM_GROUPS; g += TOTAL_WARPS) {
        // group -> (b, t0): 256 groups per batch.
        const int b  = g >> 8;
        const int t0 = (g & 255) * ROWS_PER_WARP;

        // One ballot covers all 8 rows x 4 stripes.
        const int lo = __ldg(&bgn[b * STRIPES + s]);
        const int hi = lo + __ldg(&dist[b * STRIPES + s]);
        const bool in_stripe = ((t0 + k) >= lo) && ((t0 + k) < hi);
        const unsigned m = __ballot_sync(0xFFFFFFFFu, in_stripe);
        const int pb = __ldg(&perm[b]);

        // 8 independent LDG.128 (int indexing: max idx 8.4M < 2^31).
        float4 v[ROWS_PER_WARP];
        #pragma unroll
        for (int r = 0; r < ROWS_PER_WARP; r++) {
            const int src = ((m >> (4 * r)) & 0xF) ? pb : b;
            const int src_idx = ((src << 11) | (t0 + r)) * F4 + lane;
            v[r] = x[src_idx];
        }

        // 8 coalesced STG.128 (plain stores; cache hints tested neutral in R4).
        const int dst_base = ((b << 11) | t0) * F4 + lane;
        #pragma unroll
        for (int r = 0; r < ROWS_PER_WARP; r++) {
            out[dst_base + r * F4] = v[r];
        }
    }
}

extern "C" void kernel_launch(void* const* d_in, const int* in_sizes, int n_in,
                              void* d_out, int out_size)
{
    const float4* x    = (const float4*)d_in[0];   // (128,1,2048,128) fp32
    const int*    perm = (const int*)   d_in[1];   // (128,)
    const int*    bgn  = (const int*)   d_in[2];   // (128,4)
    const int*    dist = (const int*)   d_in[3];   // (128,4)
    float4*       out  = (float4*)d_out;

    cutstripes_kernel<<<NUM_BLOCKS, 256>>>(x, perm, bgn, dist, out);
}

// round 7
// speedup vs baseline: 1.0410x; 1.0410x over previous
#include <cuda_runtime.h>

// CutStripes: out[b, :, t, :] = x[perm[b], :, t, :] if t falls inside any of 4
// stripes [bgn[b,s], bgn[b,s]+distance[b,s]), else x[b, :, t, :].
// Shapes: B=128, C=1, T=2048, F=128, STRIPES=4.
//
// R6: revert persistent grid (R5 regressed); back to one-shot 4096 blocks.
// New lever: 256-bit accesses via double4 (32B, natively 32B-aligned type).
// Blackwell sm_100 has LDG.256/STG.256; halving the request count doubles the
// bytes-in-flight ceiling at fixed MSHR/queue entries per SM — the suspected
// cause of the 38-41us plateau across R2/R3/R4 (all issued identical numbers
// of 16B requests). If ptxas splits to 2x128b, this degenerates to R2 (safe).
//
// Layout: row = 512B = 16 double4. Group = 8 rows = 128 double4 = 4/thread.
// Access j: row = (lane>>4) + 2j, col = lane&15 -> warp covers 1KB contiguous.

#define T_DIM         2048
#define D4            16        // 128 floats = 16 double4 per row
#define STRIPES       4
#define ROWS_PER_WARP 8
#define WARPS_PER_BLK 8

__global__ __launch_bounds__(256) void cutstripes_kernel(
    const double4* __restrict__ x,
    const int*     __restrict__ perm,
    const int*     __restrict__ bgn,
    const int*     __restrict__ dist,
    double4*       __restrict__ out)
{
    const int warp = (blockIdx.x * blockDim.x + threadIdx.x) >> 5;  // group id
    const int lane = threadIdx.x & 31;

    // group -> (b, t0): 256 groups per batch of 8 consecutive t rows.
    const int b  = warp >> 8;
    const int t0 = (warp & 255) * ROWS_PER_WARP;

    // Lane l checks row k=l>>2, stripe s=l&3 -> one ballot covers 8 rows.
    const int k = lane >> 2;
    const int s = lane & 3;
    const int lo = __ldg(&bgn[b * STRIPES + s]);
    const int hi = lo + __ldg(&dist[b * STRIPES + s]);
    const bool in_stripe = ((t0 + k) >= lo) && ((t0 + k) < hi);
    const unsigned m = __ballot_sync(0xFFFFFFFFu, in_stripe);
    const int pb = __ldg(&perm[b]);

    const int row0 = lane >> 4;     // 0 or 1: which row this lane starts on
    const int col  = lane & 15;     // double4 column within row

    // 4 independent 32B loads, front-batched.
    double4 v[4];
    #pragma unroll
    for (int j = 0; j < 4; j++) {
        const int row = row0 + 2 * j;
        const int src = ((m >> (4 * row)) & 0xF) ? pb : b;
        const int src_idx = ((src << 11) | (t0 + row)) * D4 + col;
        v[j] = x[src_idx];
    }

    // 4 coalesced 32B stores (warp writes 1KB contiguous per access).
    #pragma unroll
    for (int j = 0; j < 4; j++) {
        const int row = row0 + 2 * j;
        const int dst_idx = ((b << 11) | (t0 + row)) * D4 + col;
        out[dst_idx] = v[j];
    }
}

extern "C" void kernel_launch(void* const* d_in, const int* in_sizes, int n_in,
                              void* d_out, int out_size)
{
    const double4* x    = (const double4*)d_in[0];  // (128,1,2048,128) fp32
    const int*     perm = (const int*)    d_in[1];  // (128,)
    const int*     bgn  = (const int*)    d_in[2];  // (128,4)
    const int*     dist = (const int*)    d_in[3];  // (128,4)
    double4*       out  = (double4*)d_out;

    const int groups = 128 * T_DIM / ROWS_PER_WARP;   // 32768
    const int blocks = groups / WARPS_PER_BLK;        // 4096

    cutstripes_kernel<<<blocks, 256>>>(x, perm, bgn, dist, out);
}

// round 10
// speedup vs baseline: 1.1012x; 1.0578x over previous
#include <cuda_runtime.h>

// CutStripes: out[b, :, t, :] = x[perm[b], :, t, :] if t falls inside any of 4
// stripes [bgn[b,s], bgn[b,s]+distance[b,s]), else x[b, :, t, :].
// Shapes: B=128, C=1, T=2048, F=128, STRIPES=4.
//
// R9 = R7 resubmitted (R8 and R9 benches were infra failures; kernel never ran).
// Converged configuration; evidence across R2-R6:
//   - 128-bit accesses are optimal (256-bit double4 regressed: L1 replay wfs).
//   - MLP is not binding (cp.async MLP=8 == register path) -> plain LDG.128.
//   - One-shot 4096-block launch beats persistent grid by 7%.
//   - Plain stores beat st.cs (38.18 vs 38.98 ncu).
//   - All-int indexing: minimal IMAD chains, regs=32, occ ~80%.
// Sits at the mixed-R/W DRAM ceiling (~7.0 TB/s effective of 8 TB/s spec,
// 268 MB mandatory traffic -> ~38 us kernel floor).

#define T_DIM         2048
#define F4            32        // 128 floats / 4
#define STRIPES       4
#define ROWS_PER_WARP 8
#define WARPS_PER_BLK 8

__global__ __launch_bounds__(256) void cutstripes_kernel(
    const float4* __restrict__ x,
    const int*    __restrict__ perm,
    const int*    __restrict__ bgn,
    const int*    __restrict__ dist,
    float4*       __restrict__ out)
{
    const int warp = (blockIdx.x * blockDim.x + threadIdx.x) >> 5;  // group id
    const int lane = threadIdx.x & 31;

    // Each group = 8 consecutive t rows of one batch b (256 groups per batch).
    const int b  = warp >> 8;
    const int t0 = (warp & 255) * ROWS_PER_WARP;

    // Lane l checks row k=l>>2, stripe s=l&3 -> one ballot covers all 8 rows.
    const int k = lane >> 2;
    const int s = lane & 3;
    const int lo = __ldg(&bgn[b * STRIPES + s]);
    const int hi = lo + __ldg(&dist[b * STRIPES + s]);
    const bool in_stripe = ((t0 + k) >= lo) && ((t0 + k) < hi);
    const unsigned m = __ballot_sync(0xFFFFFFFFu, in_stripe);
    const int pb = __ldg(&perm[b]);

    // 8 independent LDG.128, front-batched (int indexing: max idx < 2^23).
    float4 v[ROWS_PER_WARP];
    #pragma unroll
    for (int r = 0; r < ROWS_PER_WARP; r++) {
        const int src = ((m >> (4 * r)) & 0xF) ? pb : b;
        const int src_idx = ((src << 11) | (t0 + r)) * F4 + lane;
        v[r] = x[src_idx];
    }

    // 8 coalesced STG.128 (plain write-back stores; hints measured worse).
    const int dst_base = ((b << 11) | t0) * F4 + lane;
    #pragma unroll
    for (int r = 0; r < ROWS_PER_WARP; r++) {
        out[dst_base + r * F4] = v[r];
    }
}

extern "C" void kernel_launch(void* const* d_in, const int* in_sizes, int n_in,
                              void* d_out, int out_size)
{
    const float4* x    = (const float4*)d_in[0];   // (128,1,2048,128) fp32
    const int*    perm = (const int*)   d_in[1];   // (128,)
    const int*    bgn  = (const int*)   d_in[2];   // (128,4)
    const int*    dist = (const int*)   d_in[3];   // (128,4)
    float4*       out  = (float4*)d_out;

    const int groups = 128 * T_DIM / ROWS_PER_WARP;   // 32768
    const int blocks = groups / WARPS_PER_BLK;        // 4096

    cutstripes_kernel<<<blocks, 256>>>(x, perm, bgn, dist, out);
}